// round 8
// baseline (speedup 1.0000x reference)
#include <cuda_runtime.h>
#include <cuda_fp16.h>
#include <cstdint>

// ============================================================================
// Problem: B=4, Lq=Lk=4096, D=512, fp32. Output = (context, attn) concatenated.
// ============================================================================
#define BATCH 4
#define LSEQ  4096
#define DDIM  512
#define NELEM (BATCH * LSEQ * DDIM)              // 8,388,608
#define CTX_ELEMS ((size_t)BATCH * LSEQ * DDIM)
#define PELEMS ((size_t)BATCH * LSEQ * LSEQ)     // 67,108,864

// Scratch (device globals: sanctioned allocation-free scratch)
__device__ __align__(16) __half g_Qh[NELEM];     // fp16(Q)
__device__ __align__(16) __half g_Vh[NELEM];     // fp16(V)
__device__ __align__(16) __half g_VTh[NELEM];    // [B, D, Lk] fp16(V^T)
__device__ __align__(16) __half g_Ph[PELEMS];    // fp16 softmaxed P (from G2)
// int8 correction operands, per-row chunk-concatenated layout:
// row r (length 1024): for chunk c (0..7): bytes [c*128 .. c*128+63] = hi part,
// [c*128+64 .. c*128+127] = lo part.
//  Qc8: hi = rn(q*16),      lo = rn((q - fp16(q)) * 32768)
//  Vc8: hi = rn(vl*32768),  lo = rn(v*16)     (pairing: q_hi*v_lo + q_lo*v_hi)
__device__ __align__(16) int8_t g_Qc8[(size_t)NELEM * 2];
__device__ __align__(16) int8_t g_Vc8[(size_t)NELEM * 2];

#define CORR_SCALE (1.0f / 524288.0f)   // 2^-19 = (16 * 32768)^-1

// ============================================================================
// Helpers
// ============================================================================
__device__ __forceinline__ uint32_t smem_to_u32(const void* smem_ptr) {
    uint32_t addr;
    asm("{ .reg .u64 tmp; cvta.to.shared.u64 tmp, %1; cvt.u32.u64 %0, tmp; }"
        : "=r"(addr) : "l"(smem_ptr));
    return addr;
}

__device__ __forceinline__ void ldsm_x4(uint32_t (&r)[4], uint32_t addr) {
    asm volatile("ldmatrix.sync.aligned.m8n8.x4.shared.b16 {%0,%1,%2,%3}, [%4];"
                 : "=r"(r[0]), "=r"(r[1]), "=r"(r[2]), "=r"(r[3]) : "r"(addr));
}

// fp32-accum HMMA
__device__ __forceinline__ void mma16816(float (&d)[4], const uint32_t (&a)[4],
                                         uint32_t b0, uint32_t b1) {
    asm volatile(
        "mma.sync.aligned.m16n8k16.row.col.f32.f16.f16.f32 "
        "{%0,%1,%2,%3}, {%4,%5,%6,%7}, {%8,%9}, {%0,%1,%2,%3};"
        : "+f"(d[0]), "+f"(d[1]), "+f"(d[2]), "+f"(d[3])
        : "r"(a[0]), "r"(a[1]), "r"(a[2]), "r"(a[3]), "r"(b0), "r"(b1));
}

// int8 IMMA k32, s32 accumulate (2x HMMA rate)
__device__ __forceinline__ void imma16832(int (&d)[4], const uint32_t (&a)[4],
                                          uint32_t b0, uint32_t b1) {
    asm volatile(
        "mma.sync.aligned.m16n8k32.row.col.s32.s8.s8.s32 "
        "{%0,%1,%2,%3}, {%4,%5,%6,%7}, {%8,%9}, {%0,%1,%2,%3};"
        : "+r"(d[0]), "+r"(d[1]), "+r"(d[2]), "+r"(d[3])
        : "r"(a[0]), "r"(a[1]), "r"(a[2]), "r"(a[3]), "r"(b0), "r"(b1));
}

__device__ __forceinline__ uint32_t sw128(uint32_t off) {
    return off ^ ((off >> 3) & 0x70);
}

__device__ __forceinline__ int8_t to8(float x) {
    int v = __float2int_rn(x);
    v = max(-127, min(127, v));
    return (int8_t)v;
}

// cp.async 16B
__device__ __forceinline__ void cp16(uint32_t s, const void* g) {
    asm volatile("cp.async.cg.shared.global [%0], [%1], 16;" :: "r"(s), "l"(g));
}
#define CP_COMMIT() asm volatile("cp.async.commit_group;" ::: "memory")
#define CP_WAIT(n)  asm volatile("cp.async.wait_group %0;" :: "n"(n) : "memory")

// G1 smem: 3 stages x (AH + BH + A8 + B8 = 64 KB)
#define G1_STAGE 65536
#define SMEM_G1 (3 * G1_STAGE + 1024)

// G3 smem: 2 stages x (AH + BH) = 2 x 32 KB
#define G3_STAGE 32768
#define SMEM_G3 (2 * G3_STAGE + 1024)

// ============================================================================
// P0a: convert Q,V -> fp16 (hh operands) + int8 chunk-concatenated corrections
// ============================================================================
__global__ void convert_qv(const float* __restrict__ Q, const float* __restrict__ V) {
    size_t i = (size_t)blockIdx.x * 256 + threadIdx.x;
    int r = (int)(i >> 9), d = (int)(i & 511);
    size_t base = (size_t)r * 1024 + (size_t)((d >> 6) << 7) + (d & 63);

    float q = Q[i];
    __half qh = __float2half_rn(q);
    g_Qh[i] = qh;
    float ql = q - __half2float(qh);
    g_Qc8[base]      = to8(q * 16.0f);        // hi slot
    g_Qc8[base + 64] = to8(ql * 32768.0f);    // lo slot

    float v = V[i];
    __half vh = __float2half_rn(v);
    g_Vh[i] = vh;
    float vl = v - __half2float(vh);
    g_Vc8[base]      = to8(vl * 32768.0f);    // pairs with q hi
    g_Vc8[base + 64] = to8(v * 16.0f);        // pairs with q lo
}

// ============================================================================
// P0b: transpose+convert V -> VT[b][d][k] fp16
// ============================================================================
__global__ void transpose_conv(const float* __restrict__ V) {
    __shared__ float tile[32][33];
    int b = blockIdx.z;
    int k0 = blockIdx.x * 32, d0 = blockIdx.y * 32;
    int tx = threadIdx.x, ty = threadIdx.y;  // 32 x 8
#pragma unroll
    for (int j = 0; j < 4; j++) {
        tile[ty + 8 * j][tx] =
            V[((size_t)b * LSEQ + k0 + ty + 8 * j) * DDIM + d0 + tx];
    }
    __syncthreads();
#pragma unroll
    for (int j = 0; j < 4; j++) {
        int d = d0 + ty + 8 * j, k = k0 + tx;
        size_t o = ((size_t)b * DDIM + d) * LSEQ + k;
        g_VTh[o] = __float2half_rn(tile[tx][ty + 8 * j]);
    }
}

// ============================================================================
// cp.async tile loader: 128 rows x 128 bytes, SW128 swizzled, 256 threads
// ============================================================================
__device__ __forceinline__ void tile_cp(uint32_t sbase, const void* __restrict__ gsrc,
                                        int rowStrideU4, int chunk, int tid) {
    const uint4* g = reinterpret_cast<const uint4*>(gsrc);
#pragma unroll
    for (int it = 0; it < 4; it++) {
        int idx = tid + 256 * it;
        int r = idx >> 3, s = idx & 7;
        cp16(sbase + sw128((uint32_t)(r * 128 + s * 16)),
             g + (size_t)r * rowStrideU4 + (size_t)chunk * 8 + s);
    }
}

// ============================================================================
// G1 warp MMA core. Warp tile 32(m) x 64(n).
// hh -> fp16/fp32 HMMA; merged corrections -> one int8 k32 IMMA (s32 acc).
// Stage layout: AH=0, BH=16384, A8=32768, B8=49152.
// ============================================================================
struct Frag {
    uint32_t ah[2][4], a8[2][4];
    uint32_t bh[4][4], b8[4][4];
};

__device__ __forceinline__ void load_frags(Frag& f, uint32_t st,
                                           int mw, int nw, int kk, int lane) {
    int kb = kk * 32 + ((lane >> 4) << 4);
#pragma unroll
    for (int mb = 0; mb < 2; mb++) {
        int row = mw * 32 + mb * 16 + (lane & 15);
        uint32_t off = row * 128 + (kb ^ ((row & 7) << 4));
        ldsm_x4(f.ah[mb], st + off);
        ldsm_x4(f.a8[mb], st + 32768 + off);
    }
#pragma unroll
    for (int p = 0; p < 4; p++) {
        int row = nw * 64 + p * 16 + ((lane >> 3 & 1) << 3) + (lane & 7);
        uint32_t off = row * 128 + (kb ^ ((row & 7) << 4));
        ldsm_x4(f.bh[p], st + 16384 + off);
        ldsm_x4(f.b8[p], st + 49152 + off);
    }
}

__device__ __forceinline__ void mma_g1(float (&accf)[2][8][4],
                                       int (&accs)[2][8][4], const Frag& f) {
#pragma unroll
    for (int mb = 0; mb < 2; mb++)
#pragma unroll
        for (int nb = 0; nb < 8; nb++) {
            int p = nb >> 1, s = nb & 1;
            mma16816(accf[mb][nb], f.ah[mb], f.bh[p][s], f.bh[p][s + 2]);
            imma16832(accs[mb][nb], f.a8[mb], f.b8[p][s], f.b8[p][s + 2]);
        }
}

// ============================================================================
// G3 warp MMA core (single product: P_h x V_h).
// ============================================================================
struct FragG3 {
    uint32_t ah[2][4];
    uint32_t bh[4][4];
};

__device__ __forceinline__ void load_frags_g3(FragG3& f, uint32_t tA, uint32_t tB,
                                              int mw, int nw, int kk, int lane) {
    int kb = kk * 32 + ((lane >> 4) << 4);
#pragma unroll
    for (int mb = 0; mb < 2; mb++) {
        int row = mw * 32 + mb * 16 + (lane & 15);
        ldsm_x4(f.ah[mb], tA + row * 128 + (kb ^ ((row & 7) << 4)));
    }
#pragma unroll
    for (int p = 0; p < 4; p++) {
        int row = nw * 64 + p * 16 + ((lane >> 3 & 1) << 3) + (lane & 7);
        ldsm_x4(f.bh[p], tB + row * 128 + (kb ^ ((row & 7) << 4)));
    }
}

__device__ __forceinline__ void mma_1prod(float (&acc)[2][8][4], const FragG3& f) {
#pragma unroll
    for (int mb = 0; mb < 2; mb++)
#pragma unroll
        for (int nb = 0; nb < 8; nb++) {
            int p = nb >> 1, s = nb & 1;
            mma16816(acc[mb][nb], f.ah[mb], f.bh[p][s], f.bh[p][s + 2]);
        }
}

// ============================================================================
// G1: raw scores S = Q @ V^T. CTA tile 128(q) x 128(k), K=512 in 8 chunks.
// 3-stage cp.async pipeline. grid (kt=32, qt=32, b=4), 256 threads.
// ============================================================================
__global__ void __launch_bounds__(256) g1_scores(float* __restrict__ attn) {
    extern __shared__ char smem[];
    uint32_t sb0 = smem_to_u32(smem);
    uint32_t tb = (sb0 + 1023) & ~1023u;
    int tid = threadIdx.x, wid = tid >> 5, lane = tid & 31;
    int mw = wid & 3, nw = wid >> 2;
    int kt = blockIdx.x, qt = blockIdx.y, b = blockIdx.z;

    const __half*  pQh = g_Qh  + ((size_t)(b * LSEQ + qt * 128)) * DDIM;
    const __half*  pVh = g_Vh  + ((size_t)(b * LSEQ + kt * 128)) * DDIM;
    const int8_t*  pQ8 = g_Qc8 + ((size_t)(b * LSEQ + qt * 128)) * 1024;
    const int8_t*  pV8 = g_Vc8 + ((size_t)(b * LSEQ + kt * 128)) * 1024;

    float accf[2][8][4];
    int accs[2][8][4];
#pragma unroll
    for (int i = 0; i < 2; i++)
#pragma unroll
        for (int j = 0; j < 8; j++)
#pragma unroll
            for (int k = 0; k < 4; k++) { accf[i][j][k] = 0.f; accs[i][j][k] = 0; }

    auto issue = [&](int c) {
        uint32_t st = tb + (uint32_t)(c % 3) * G1_STAGE;
        tile_cp(st,         pQh, DDIM / 8, c, tid);   // fp16 Q rows: 128B = 64 halfs
        tile_cp(st + 16384, pVh, DDIM / 8, c, tid);
        tile_cp(st + 32768, pQ8, 64,       c, tid);   // int8 rows: stride 1024B = 64 u4
        tile_cp(st + 49152, pV8, 64,       c, tid);
        CP_COMMIT();
    };

    issue(0);
    issue(1);
    for (int c = 0; c < 8; c++) {
        if (c < 6) {
            issue(c + 2);
            CP_WAIT(2);
        } else if (c == 6) {
            CP_WAIT(1);
        } else {
            CP_WAIT(0);
        }
        __syncthreads();
        uint32_t st = tb + (uint32_t)(c % 3) * G1_STAGE;
#pragma unroll
        for (int kk = 0; kk < 4; kk++) {
            Frag f;
            load_frags(f, st, mw, nw, kk, lane);
            mma_g1(accf, accs, f);
        }
        __syncthreads();
    }

    // Epilogue: merge scaled int corrections and write raw scores
    int gid = lane >> 2, tig = lane & 3;
    size_t base = ((size_t)(b * LSEQ + qt * 128 + mw * 32)) * LSEQ
                + (size_t)kt * 128 + nw * 64;
#pragma unroll
    for (int mb = 0; mb < 2; mb++)
#pragma unroll
        for (int nb = 0; nb < 8; nb++) {
            size_t o0 = base + (size_t)(mb * 16 + gid) * LSEQ + nb * 8 + tig * 2;
            *reinterpret_cast<float2*>(&attn[o0]) = make_float2(
                accf[mb][nb][0] + (float)accs[mb][nb][0] * CORR_SCALE,
                accf[mb][nb][1] + (float)accs[mb][nb][1] * CORR_SCALE);
            *reinterpret_cast<float2*>(&attn[o0 + 8 * LSEQ]) = make_float2(
                accf[mb][nb][2] + (float)accs[mb][nb][2] * CORR_SCALE,
                accf[mb][nb][3] + (float)accs[mb][nb][3] * CORR_SCALE);
        }
}

// ============================================================================
// G2: single-pass register-resident row softmax. One block per row.
// Writes fp32 p to attn AND fp16 p to g_Ph (feeds G3's A tiles).
// ============================================================================
__global__ void __launch_bounds__(256) g2_softmax(float* __restrict__ attn) {
    __shared__ float red[16];
    int tid = threadIdx.x, lane = tid & 31, w = tid >> 5;
    float4* row = reinterpret_cast<float4*>(attn + (size_t)blockIdx.x * LSEQ);
    __half2* hrow = reinterpret_cast<__half2*>(g_Ph + (size_t)blockIdx.x * LSEQ);

    float4 v[4];
#pragma unroll
    for (int i = 0; i < 4; i++) v[i] = row[tid + i * 256];

    float m = -3.4e38f;
#pragma unroll
    for (int i = 0; i < 4; i++)
        m = fmaxf(m, fmaxf(fmaxf(v[i].x, v[i].y), fmaxf(v[i].z, v[i].w)));
#pragma unroll
    for (int o = 16; o; o >>= 1) m = fmaxf(m, __shfl_xor_sync(~0u, m, o));
    if (lane == 0) red[w] = m;
    __syncthreads();
    m = red[0];
#pragma unroll
    for (int i = 1; i < 8; i++) m = fmaxf(m, red[i]);

    float z = 0.f;
#pragma unroll
    for (int i = 0; i < 4; i++) {
        v[i].x = __expf(v[i].x - m);
        v[i].y = __expf(v[i].y - m);
        v[i].z = __expf(v[i].z - m);
        v[i].w = __expf(v[i].w - m);
        z += (v[i].x + v[i].y) + (v[i].z + v[i].w);
    }
#pragma unroll
    for (int o = 16; o; o >>= 1) z += __shfl_xor_sync(~0u, z, o);
    if (lane == 0) red[8 + w] = z;
    __syncthreads();
    z = 0.f;
#pragma unroll
    for (int i = 0; i < 8; i++) z += red[8 + i];
    float iz = 1.0f / z;

#pragma unroll
    for (int i = 0; i < 4; i++) {
        v[i].x *= iz; v[i].y *= iz; v[i].z *= iz; v[i].w *= iz;
        row[tid + i * 256] = v[i];
        hrow[2 * (tid + i * 256)]     = __floats2half2_rn(v[i].x, v[i].y);
        hrow[2 * (tid + i * 256) + 1] = __floats2half2_rn(v[i].z, v[i].w);
    }
}

// ============================================================================
// G3: context C = P @ V. CTA tile 128(q) x 128(d), K=4096 in 64 chunks.
// Single-product (P_h x V_h), 2-stage cp.async. grid (dt=4, qt=32, b=4).
// ============================================================================
__global__ void __launch_bounds__(256) g3_context(float* __restrict__ ctx) {
    extern __shared__ char smem[];
    uint32_t sb0 = smem_to_u32(smem);
    uint32_t tb = (sb0 + 1023) & ~1023u;
    int tid = threadIdx.x, wid = tid >> 5, lane = tid & 31;
    int mw = wid & 3, nw = wid >> 2;
    int dt = blockIdx.x, qt = blockIdx.y, b = blockIdx.z;

    const __half* pA  = g_Ph  + ((size_t)(b * LSEQ + qt * 128)) * LSEQ;
    const __half* pBh = g_VTh + ((size_t)(b * DDIM + dt * 128)) * LSEQ;

    float acc[2][8][4];
#pragma unroll
    for (int i = 0; i < 2; i++)
#pragma unroll
        for (int j = 0; j < 8; j++)
#pragma unroll
            for (int k = 0; k < 4; k++) acc[i][j][k] = 0.f;

    auto issue = [&](int c, int s) {
        uint32_t st = tb + s * G3_STAGE;
        tile_cp(st,         pA,  LSEQ / 8, c, tid);
        tile_cp(st + 16384, pBh, LSEQ / 8, c, tid);
        CP_COMMIT();
    };

    issue(0, 0);
    for (int c = 0; c < 64; c++) {
        if (c < 63) {
            issue(c + 1, (c + 1) & 1);
            CP_WAIT(1);
        } else {
            CP_WAIT(0);
        }
        __syncthreads();
        uint32_t st = tb + (c & 1) * G3_STAGE;
#pragma unroll
        for (int kk = 0; kk < 4; kk++) {
            FragG3 f;
            load_frags_g3(f, st, st + 16384, mw, nw, kk, lane);
            mma_1prod(acc, f);
        }
        __syncthreads();
    }

    // Epilogue: write context
    int gid = lane >> 2, tig = lane & 3;
    size_t base = ((size_t)(b * LSEQ + qt * 128 + mw * 32)) * DDIM
                + (size_t)dt * 128 + nw * 64;
#pragma unroll
    for (int mb = 0; mb < 2; mb++)
#pragma unroll
        for (int nb = 0; nb < 8; nb++) {
            size_t o0 = base + (size_t)(mb * 16 + gid) * DDIM + nb * 8 + tig * 2;
            *reinterpret_cast<float2*>(&ctx[o0]) =
                make_float2(acc[mb][nb][0], acc[mb][nb][1]);
            *reinterpret_cast<float2*>(&ctx[o0 + 8 * DDIM]) =
                make_float2(acc[mb][nb][2], acc[mb][nb][3]);
        }
}

// ============================================================================
// Launch
// ============================================================================
extern "C" void kernel_launch(void* const* d_in, const int* in_sizes, int n_in,
                              void* d_out, int out_size) {
    (void)in_sizes; (void)n_in; (void)out_size;
    const float* query = (const float*)d_in[0];
    const float* value = (const float*)d_in[1];
    float* out = (float*)d_out;
    float* ctx  = out;               // context first
    float* attn = out + CTX_ELEMS;   // then attn

    cudaFuncSetAttribute(g1_scores,  cudaFuncAttributeMaxDynamicSharedMemorySize, SMEM_G1);
    cudaFuncSetAttribute(g3_context, cudaFuncAttributeMaxDynamicSharedMemorySize, SMEM_G3);

    convert_qv<<<NELEM / 256, 256>>>(query, value);
    transpose_conv<<<dim3(LSEQ / 32, DDIM / 32, BATCH), dim3(32, 8)>>>(value);
    g1_scores<<<dim3(32, 32, 4), 256, SMEM_G1>>>(attn);
    g2_softmax<<<BATCH * LSEQ, 256>>>(attn);
    g3_context<<<dim3(4, 32, 4), 256, SMEM_G3>>>(ctx);
}

// round 9
// speedup vs baseline: 1.7570x; 1.7570x over previous
#include <cuda_runtime.h>
#include <cuda_fp16.h>
#include <cstdint>

// ============================================================================
// Problem: B=4, Lq=Lk=4096, D=512, fp32. Output = (context, attn) concatenated.
// ============================================================================
#define BATCH 4
#define LSEQ  4096
#define DDIM  512
#define NELEM (BATCH * LSEQ * DDIM)              // 8,388,608
#define CTX_ELEMS ((size_t)BATCH * LSEQ * DDIM)
#define PELEMS ((size_t)BATCH * LSEQ * LSEQ)     // 67,108,864

// fp16 hi/lo split scratch (device globals: sanctioned allocation-free scratch)
__device__ __align__(16) __half g_Qh[NELEM];
__device__ __align__(16) __half g_Ql[NELEM];
__device__ __align__(16) __half g_Vh[NELEM];
__device__ __align__(16) __half g_Vl[NELEM];
__device__ __align__(16) __half g_VTh[NELEM];  // [B, D, Lk] (hi only; G3 is 1-product)
__device__ __align__(16) __half g_Ph[PELEMS];  // fp16 softmaxed P (written by G2)

// ============================================================================
// Helpers
// ============================================================================
__device__ __forceinline__ uint32_t smem_to_u32(const void* smem_ptr) {
    uint32_t addr;
    asm("{ .reg .u64 tmp; cvta.to.shared.u64 tmp, %1; cvt.u32.u64 %0, tmp; }"
        : "=r"(addr) : "l"(smem_ptr));
    return addr;
}

__device__ __forceinline__ void ldsm_x4(uint32_t (&r)[4], uint32_t addr) {
    asm volatile("ldmatrix.sync.aligned.m8n8.x4.shared.b16 {%0,%1,%2,%3}, [%4];"
                 : "=r"(r[0]), "=r"(r[1]), "=r"(r[2]), "=r"(r[3]) : "r"(addr));
}

// fp32-accum HMMA
__device__ __forceinline__ void mma16816(float (&d)[4], const uint32_t (&a)[4],
                                         uint32_t b0, uint32_t b1) {
    asm volatile(
        "mma.sync.aligned.m16n8k16.row.col.f32.f16.f16.f32 "
        "{%0,%1,%2,%3}, {%4,%5,%6,%7}, {%8,%9}, {%0,%1,%2,%3};"
        : "+f"(d[0]), "+f"(d[1]), "+f"(d[2]), "+f"(d[3])
        : "r"(a[0]), "r"(a[1]), "r"(a[2]), "r"(a[3]), "r"(b0), "r"(b1));
}

// fp16-accum HMMA (for small correction products)
__device__ __forceinline__ void mma16816h(uint32_t (&d)[2], const uint32_t (&a)[4],
                                          uint32_t b0, uint32_t b1) {
    asm volatile(
        "mma.sync.aligned.m16n8k16.row.col.f16.f16.f16.f16 "
        "{%0,%1}, {%2,%3,%4,%5}, {%6,%7}, {%0,%1};"
        : "+r"(d[0]), "+r"(d[1])
        : "r"(a[0]), "r"(a[1]), "r"(a[2]), "r"(a[3]), "r"(b0), "r"(b1));
}

__device__ __forceinline__ uint32_t sw128(uint32_t off) {
    return off ^ ((off >> 3) & 0x70);
}

// cp.async 16B
__device__ __forceinline__ void cp16(uint32_t s, const void* g) {
    asm volatile("cp.async.cg.shared.global [%0], [%1], 16;" :: "r"(s), "l"(g));
}
#define CP_COMMIT() asm volatile("cp.async.commit_group;" ::: "memory")
#define CP_WAIT(n)  asm volatile("cp.async.wait_group %0;" :: "n"(n) : "memory")

// G1 smem: 3 stages x (AH+AL+BH+BL = 64 KB)
#define G1_STAGE 65536
#define SMEM_G1 (3 * G1_STAGE + 1024)

// G3 smem: 2 stages x (AH + BH) = 2 x 32 KB
#define G3_STAGE 32768
#define SMEM_G3 (2 * G3_STAGE + 1024)

// ============================================================================
// P0a: elementwise convert Q,V -> fp16 hi/lo
// ============================================================================
__global__ void convert_qv(const float* __restrict__ Q, const float* __restrict__ V) {
    size_t i = (size_t)blockIdx.x * 256 + threadIdx.x;
    float q = Q[i];
    __half qh = __float2half_rn(q);
    g_Qh[i] = qh;
    g_Ql[i] = __float2half_rn(q - __half2float(qh));
    float v = V[i];
    __half vh = __float2half_rn(v);
    g_Vh[i] = vh;
    g_Vl[i] = __float2half_rn(v - __half2float(vh));
}

// ============================================================================
// P0b: transpose+convert V -> VT[b][d][k] fp16 (hi only)
// ============================================================================
__global__ void transpose_conv(const float* __restrict__ V) {
    __shared__ float tile[32][33];
    int b = blockIdx.z;
    int k0 = blockIdx.x * 32, d0 = blockIdx.y * 32;
    int tx = threadIdx.x, ty = threadIdx.y;  // 32 x 8
#pragma unroll
    for (int j = 0; j < 4; j++) {
        tile[ty + 8 * j][tx] =
            V[((size_t)b * LSEQ + k0 + ty + 8 * j) * DDIM + d0 + tx];
    }
    __syncthreads();
#pragma unroll
    for (int j = 0; j < 4; j++) {
        int d = d0 + ty + 8 * j, k = k0 + tx;
        size_t o = ((size_t)b * DDIM + d) * LSEQ + k;
        g_VTh[o] = __float2half_rn(tile[tx][ty + 8 * j]);
    }
}

// Tiny probe so the ncu fixed-skip profiling slot lands on g1_scores.
__global__ void probe_kernel() {}

// ============================================================================
// cp.async tile loader: 128 rows x 64 halfs, SW128 swizzled, 256 threads
// ============================================================================
__device__ __forceinline__ void tile_cp(uint32_t sbase,
                                        const __half* __restrict__ gsrc,
                                        int rowStrideU4, int chunk, int tid) {
    const uint4* g = reinterpret_cast<const uint4*>(gsrc);
#pragma unroll
    for (int it = 0; it < 4; it++) {
        int idx = tid + 256 * it;
        int r = idx >> 3, s = idx & 7;
        cp16(sbase + sw128((uint32_t)(r * 128 + s * 16)),
             g + (size_t)r * rowStrideU4 + (size_t)chunk * 8 + s);
    }
}

// ============================================================================
// G1 warp MMA core. Warp tile 32(m) x 64(n). AL = AH+16384, BL = BH+16384.
// hh -> fp32 acc; hl + lh corrections -> fp16 acc.
// ============================================================================
struct Frag {
    uint32_t ah[2][4], al[2][4];
    uint32_t bh[4][4], bl[4][4];
};

__device__ __forceinline__ void load_frags(Frag& f, uint32_t tA, uint32_t tB,
                                           int mw, int nw, int kk, int lane) {
    int kb = kk * 32 + ((lane >> 4) << 4);
#pragma unroll
    for (int mb = 0; mb < 2; mb++) {
        int row = mw * 32 + mb * 16 + (lane & 15);
        uint32_t addr = tA + row * 128 + (kb ^ ((row & 7) << 4));
        ldsm_x4(f.ah[mb], addr);
        ldsm_x4(f.al[mb], addr + 16384);
    }
#pragma unroll
    for (int p = 0; p < 4; p++) {
        int row = nw * 64 + p * 16 + ((lane >> 3 & 1) << 3) + (lane & 7);
        uint32_t addr = tB + row * 128 + (kb ^ ((row & 7) << 4));
        ldsm_x4(f.bh[p], addr);
        ldsm_x4(f.bl[p], addr + 16384);
    }
}

__device__ __forceinline__ void mma_g1(float (&accf)[2][8][4],
                                       uint32_t (&acch)[2][8][2], const Frag& f) {
#pragma unroll
    for (int mb = 0; mb < 2; mb++)
#pragma unroll
        for (int nb = 0; nb < 8; nb++) {
            int p = nb >> 1, s = nb & 1;
            mma16816(accf[mb][nb], f.ah[mb], f.bh[p][s], f.bh[p][s + 2]);
            mma16816h(acch[mb][nb], f.ah[mb], f.bl[p][s], f.bl[p][s + 2]);
            mma16816h(acch[mb][nb], f.al[mb], f.bh[p][s], f.bh[p][s + 2]);
        }
}

// ============================================================================
// G3 warp MMA core (single product: P_h x V_h).
// ============================================================================
struct FragG3 {
    uint32_t ah[2][4];
    uint32_t bh[4][4];
};

__device__ __forceinline__ void load_frags_g3(FragG3& f, uint32_t tA, uint32_t tB,
                                              int mw, int nw, int kk, int lane) {
    int kb = kk * 32 + ((lane >> 4) << 4);
#pragma unroll
    for (int mb = 0; mb < 2; mb++) {
        int row = mw * 32 + mb * 16 + (lane & 15);
        ldsm_x4(f.ah[mb], tA + row * 128 + (kb ^ ((row & 7) << 4)));
    }
#pragma unroll
    for (int p = 0; p < 4; p++) {
        int row = nw * 64 + p * 16 + ((lane >> 3 & 1) << 3) + (lane & 7);
        ldsm_x4(f.bh[p], tB + row * 128 + (kb ^ ((row & 7) << 4)));
    }
}

__device__ __forceinline__ void mma_1prod(float (&acc)[2][8][4], const FragG3& f) {
#pragma unroll
    for (int mb = 0; mb < 2; mb++)
#pragma unroll
        for (int nb = 0; nb < 8; nb++) {
            int p = nb >> 1, s = nb & 1;
            mma16816(acc[mb][nb], f.ah[mb], f.bh[p][s], f.bh[p][s + 2]);
        }
}

// ============================================================================
// G1: raw scores S = Q @ V^T. CTA tile 128(q) x 128(k), K=512 in 8 chunks.
// 3-stage cp.async pipeline, ONE barrier per chunk (issue after barrier:
// the barrier proves all warps finished chunk c-1, so overwriting stage
// (c+2)%3 == (c-1)%3 is safe). grid (kt=32, qt=32, b=4), 256 threads.
// ============================================================================
__global__ void __launch_bounds__(256) g1_scores(float* __restrict__ attn) {
    extern __shared__ char smem[];
    uint32_t sb0 = smem_to_u32(smem);
    uint32_t tb = (sb0 + 1023) & ~1023u;
    int tid = threadIdx.x, wid = tid >> 5, lane = tid & 31;
    int mw = wid & 3, nw = wid >> 2;
    int kt = blockIdx.x, qt = blockIdx.y, b = blockIdx.z;

    const __half* pQh = g_Qh + ((size_t)(b * LSEQ + qt * 128)) * DDIM;
    const __half* pQl = g_Ql + ((size_t)(b * LSEQ + qt * 128)) * DDIM;
    const __half* pVh = g_Vh + ((size_t)(b * LSEQ + kt * 128)) * DDIM;
    const __half* pVl = g_Vl + ((size_t)(b * LSEQ + kt * 128)) * DDIM;

    float accf[2][8][4];
    uint32_t acch[2][8][2];
#pragma unroll
    for (int i = 0; i < 2; i++)
#pragma unroll
        for (int j = 0; j < 8; j++) {
#pragma unroll
            for (int k = 0; k < 4; k++) accf[i][j][k] = 0.f;
            acch[i][j][0] = 0u;
            acch[i][j][1] = 0u;
        }

    auto issue = [&](int c) {
        uint32_t st = tb + (uint32_t)(c % 3) * G1_STAGE;
        tile_cp(st,         pQh, DDIM / 8, c, tid);
        tile_cp(st + 16384, pQl, DDIM / 8, c, tid);
        tile_cp(st + 32768, pVh, DDIM / 8, c, tid);
        tile_cp(st + 49152, pVl, DDIM / 8, c, tid);
        CP_COMMIT();
    };

    issue(0);
    issue(1);
    for (int c = 0; c < 8; c++) {
        if (c < 7) { CP_WAIT(1); } else { CP_WAIT(0); }   // chunk c resident
        __syncthreads();                                   // single barrier/chunk
        if (c < 6) issue(c + 2);                           // overwrites stage (c-1)%3
        uint32_t st = tb + (uint32_t)(c % 3) * G1_STAGE;
#pragma unroll
        for (int kk = 0; kk < 4; kk++) {
            Frag f;
            load_frags(f, st, st + 32768, mw, nw, kk, lane);
            mma_g1(accf, acch, f);
        }
    }

    // Epilogue: merge fp16 corrections into fp32 and write raw scores
    int gid = lane >> 2, tig = lane & 3;
    size_t base = ((size_t)(b * LSEQ + qt * 128 + mw * 32)) * LSEQ
                + (size_t)kt * 128 + nw * 64;
#pragma unroll
    for (int mb = 0; mb < 2; mb++)
#pragma unroll
        for (int nb = 0; nb < 8; nb++) {
            float2 c01 = __half22float2(*reinterpret_cast<const __half2*>(&acch[mb][nb][0]));
            float2 c23 = __half22float2(*reinterpret_cast<const __half2*>(&acch[mb][nb][1]));
            size_t o0 = base + (size_t)(mb * 16 + gid) * LSEQ + nb * 8 + tig * 2;
            *reinterpret_cast<float2*>(&attn[o0]) =
                make_float2(accf[mb][nb][0] + c01.x, accf[mb][nb][1] + c01.y);
            *reinterpret_cast<float2*>(&attn[o0 + 8 * LSEQ]) =
                make_float2(accf[mb][nb][2] + c23.x, accf[mb][nb][3] + c23.y);
        }
}

// ============================================================================
// G2: single-pass register-resident row softmax. One block per row.
// Writes fp32 p to attn AND fp16 p to g_Ph (feeds G3's A tiles).
// ============================================================================
__global__ void __launch_bounds__(256) g2_softmax(float* __restrict__ attn) {
    __shared__ float red[16];
    int tid = threadIdx.x, lane = tid & 31, w = tid >> 5;
    float4* row = reinterpret_cast<float4*>(attn + (size_t)blockIdx.x * LSEQ);
    __half2* hrow = reinterpret_cast<__half2*>(g_Ph + (size_t)blockIdx.x * LSEQ);

    float4 v[4];
#pragma unroll
    for (int i = 0; i < 4; i++) v[i] = row[tid + i * 256];

    float m = -3.4e38f;
#pragma unroll
    for (int i = 0; i < 4; i++)
        m = fmaxf(m, fmaxf(fmaxf(v[i].x, v[i].y), fmaxf(v[i].z, v[i].w)));
#pragma unroll
    for (int o = 16; o; o >>= 1) m = fmaxf(m, __shfl_xor_sync(~0u, m, o));
    if (lane == 0) red[w] = m;
    __syncthreads();
    m = red[0];
#pragma unroll
    for (int i = 1; i < 8; i++) m = fmaxf(m, red[i]);

    float z = 0.f;
#pragma unroll
    for (int i = 0; i < 4; i++) {
        v[i].x = __expf(v[i].x - m);
        v[i].y = __expf(v[i].y - m);
        v[i].z = __expf(v[i].z - m);
        v[i].w = __expf(v[i].w - m);
        z += (v[i].x + v[i].y) + (v[i].z + v[i].w);
    }
#pragma unroll
    for (int o = 16; o; o >>= 1) z += __shfl_xor_sync(~0u, z, o);
    if (lane == 0) red[8 + w] = z;
    __syncthreads();
    z = 0.f;
#pragma unroll
    for (int i = 0; i < 8; i++) z += red[8 + i];
    float iz = 1.0f / z;

#pragma unroll
    for (int i = 0; i < 4; i++) {
        v[i].x *= iz; v[i].y *= iz; v[i].z *= iz; v[i].w *= iz;
        row[tid + i * 256] = v[i];
        hrow[2 * (tid + i * 256)]     = __floats2half2_rn(v[i].x, v[i].y);
        hrow[2 * (tid + i * 256) + 1] = __floats2half2_rn(v[i].z, v[i].w);
    }
}

// ============================================================================
// G3: context C = P @ V. CTA tile 128(q) x 128(d), K=4096 in 64 chunks.
// Single-product (P_h x V_h), 2-stage cp.async, ONE barrier per chunk.
// grid (dt=4, qt=32, b=4).
// ============================================================================
__global__ void __launch_bounds__(256) g3_context(float* __restrict__ ctx) {
    extern __shared__ char smem[];
    uint32_t sb0 = smem_to_u32(smem);
    uint32_t tb = (sb0 + 1023) & ~1023u;
    int tid = threadIdx.x, wid = tid >> 5, lane = tid & 31;
    int mw = wid & 3, nw = wid >> 2;
    int dt = blockIdx.x, qt = blockIdx.y, b = blockIdx.z;

    const __half* pA  = g_Ph  + ((size_t)(b * LSEQ + qt * 128)) * LSEQ;
    const __half* pBh = g_VTh + ((size_t)(b * DDIM + dt * 128)) * LSEQ;

    float acc[2][8][4];
#pragma unroll
    for (int i = 0; i < 2; i++)
#pragma unroll
        for (int j = 0; j < 8; j++)
#pragma unroll
            for (int k = 0; k < 4; k++) acc[i][j][k] = 0.f;

    auto issue = [&](int c) {
        uint32_t st = tb + (uint32_t)(c & 1) * G3_STAGE;
        tile_cp(st,         pA,  LSEQ / 8, c, tid);
        tile_cp(st + 16384, pBh, LSEQ / 8, c, tid);
        CP_COMMIT();
    };

    issue(0);
    for (int c = 0; c < 64; c++) {
        CP_WAIT(0);            // chunk c resident (only group pending)
        __syncthreads();       // single barrier/chunk: all warps done with c-1
        if (c < 63) issue(c + 1);   // overwrites stage (c-1)&1 — safe
        uint32_t st = tb + (uint32_t)(c & 1) * G3_STAGE;
#pragma unroll
        for (int kk = 0; kk < 4; kk++) {
            FragG3 f;
            load_frags_g3(f, st, st + 16384, mw, nw, kk, lane);
            mma_1prod(acc, f);
        }
    }

    // Epilogue: write context
    int gid = lane >> 2, tig = lane & 3;
    size_t base = ((size_t)(b * LSEQ + qt * 128 + mw * 32)) * DDIM
                + (size_t)dt * 128 + nw * 64;
#pragma unroll
    for (int mb = 0; mb < 2; mb++)
#pragma unroll
        for (int nb = 0; nb < 8; nb++) {
            size_t o0 = base + (size_t)(mb * 16 + gid) * DDIM + nb * 8 + tig * 2;
            *reinterpret_cast<float2*>(&ctx[o0]) =
                make_float2(acc[mb][nb][0], acc[mb][nb][1]);
            *reinterpret_cast<float2*>(&ctx[o0 + 8 * DDIM]) =
                make_float2(acc[mb][nb][2], acc[mb][nb][3]);
        }
}

// ============================================================================
// Launch
// ============================================================================
extern "C" void kernel_launch(void* const* d_in, const int* in_sizes, int n_in,
                              void* d_out, int out_size) {
    (void)in_sizes; (void)n_in; (void)out_size;
    const float* query = (const float*)d_in[0];
    const float* value = (const float*)d_in[1];
    float* out = (float*)d_out;
    float* ctx  = out;               // context first
    float* attn = out + CTX_ELEMS;   // then attn

    cudaFuncSetAttribute(g1_scores,  cudaFuncAttributeMaxDynamicSharedMemorySize, SMEM_G1);
    cudaFuncSetAttribute(g3_context, cudaFuncAttributeMaxDynamicSharedMemorySize, SMEM_G3);

    convert_qv<<<NELEM / 256, 256>>>(query, value);
    transpose_conv<<<dim3(LSEQ / 32, DDIM / 32, BATCH), dim3(32, 8)>>>(value);
    probe_kernel<<<1, 32>>>();   // shifts ncu's fixed profiling slot onto g1
    g1_scores<<<dim3(32, 32, 4), 256, SMEM_G1>>>(attn);
    g2_softmax<<<BATCH * LSEQ, 256>>>(attn);
    g3_context<<<dim3(4, 32, 4), 256, SMEM_G3>>>(ctx);
}